// round 14
// baseline (speedup 1.0000x reference)
#include <cuda_runtime.h>
#include <cstdint>

// ---- Problem constants -----------------------------------------------------
#define BB 16
#define NN 8192
#define NIN 4096
#define BN (BB * NN)          // 131072
#define KTOT (NN + NIN)       // 12288 virtual rows (W_int then W_ext)
#define NSPLIT 16
#define TILE_COLS 128
#define NTILES (NN / TILE_COLS)   // 64
#define CHUNK 16
#define SEG_MAX 768           // = ceil(KTOT/NSPLIT)

#define ALPHA_F 0.9512294245007140f
#define ONE_MINUS_ALPHA_F (1.0f - 0.9512294245007140f)
#define RHO_A_F 0.9950124791926823f
#define BETA_F 1.8f
#define TH0_F 1.0f

// ---- Device scratch (static globals, allowed) ------------------------------
__device__ unsigned g_umask[KTOT];                  // 16-bit batch mask per row
__device__ unsigned g_ulist[KTOT];                  // packed (mask<<16)|row
__device__ int      g_ucnt;
__device__ float    g_partial[NSPLIT * BB * NN];    // 8.4 MB split-K partials

// ---- cp.async helpers -------------------------------------------------------
#define CP_ASYNC16(dst_smem, src_gmem) \
    asm volatile("cp.async.cg.shared.global [%0], [%1], 16;" \
                 :: "r"(dst_smem), "l"(src_gmem) : "memory")
#define CP_COMMIT() asm volatile("cp.async.commit_group;" ::: "memory")
#define CP_WAIT1()  asm volatile("cp.async.wait_group 1;" ::: "memory")

// ---- Kernel 1: per-row 16-bit batch activity mask --------------------------
__global__ __launch_bounds__(512)
void k_mask(const float* __restrict__ Xd, const float* __restrict__ Xext) {
    int k = blockIdx.x * 512 + threadIdx.x;
    unsigned m = 0;
    if (k < NN) {
#pragma unroll
        for (int b = 0; b < 16; b++)
            m |= (Xd[(size_t)(7 * BB + b) * NN + k] > 0.5f ? 1u : 0u) << b;
    } else {
#pragma unroll
        for (int b = 0; b < 16; b++)
            m |= (Xext[(size_t)b * NIN + (k - NN)] > 0.5f ? 1u : 0u) << b;
    }
    g_umask[k] = m;
}

// ---- Kernel 2: compaction with warp-stripe counting (2 barriers total) -----
// 1024 threads; warp ws owns rows [ws*384, ws*384+384) = 12 ballot groups.
// Phase 1: count (masks kept in regs). Phase 2: block scan. Phase 3: scatter.
__global__ __launch_bounds__(1024)
void k_compact() {
    __shared__ int s_w[32];
    int tid = threadIdx.x, ws = tid >> 5, lane = tid & 31;
    unsigned lt = (1u << lane) - 1u;
    const int base = ws * (KTOT / 32);   // 384 rows per warp

    unsigned bal[12];
    unsigned my[12];
    int cnt = 0;
#pragma unroll
    for (int u = 0; u < 12; u++) {
        unsigned m = g_umask[base + u * 32 + lane];
        my[u] = m;
        bal[u] = __ballot_sync(0xffffffffu, m != 0);
        cnt += __popc(bal[u]);
    }
    if (lane == 0) s_w[ws] = cnt;
    __syncthreads();

    if (ws == 0) {
        int v = s_w[lane];
        int incl = v;
#pragma unroll
        for (int d = 1; d < 32; d <<= 1) {
            int o = __shfl_up_sync(0xffffffffu, incl, d);
            if (lane >= d) incl += o;
        }
        s_w[lane] = incl - v;            // exclusive offsets
        if (lane == 31) g_ucnt = incl;
    }
    __syncthreads();

    int pos = s_w[ws];
#pragma unroll
    for (int u = 0; u < 12; u++) {
        if (my[u])
            g_ulist[pos + __popc(bal[u] & lt)] =
                (my[u] << 16) | (unsigned)(base + u * 32 + lane);
        pos += __popc(bal[u]);
    }
}

// ---- Kernel 3: union-row sparse sum, 128-col tiles for 2x concurrency ------
// grid (NTILES=64, NSPLIT=16) = 1024 CTAs x 256 threads (~6 CTAs/SM).
// cp.async stages CHUNK=16 row segments (16 x 512B = 8KB) double-buffered;
// warp w accumulates batches {2w, 2w+1} in registers (static indices).
__global__ __launch_bounds__(256)
void spmm_union(const float* __restrict__ Wint,
                const float* __restrict__ Wext) {
    __shared__ unsigned s_ent[SEG_MAX];                  // 3 KB entries
    __shared__ float4   s_row[2][CHUNK][TILE_COLS / 4];  // 2 x 8 KB rows

    const int tile = blockIdx.x;
    const int s    = blockIdx.y;
    const int tid  = threadIdx.x;
    const int w    = tid >> 5;
    const int lane = tid & 31;

    int cnt = g_ucnt;
    int seg = (cnt + NSPLIT - 1) / NSPLIT;
    int start = s * seg;
    int end = start + seg; if (end > cnt) end = cnt;
    int len = end - start; if (len < 0) len = 0;

    // Stage the entry list segment into smem once.
    for (int i = tid; i < len; i += 256) s_ent[i] = g_ulist[start + i];
    __syncthreads();

    const unsigned bit0 = 1u << (2 * w);
    const unsigned bit1 = 2u << (2 * w);
    float4 a0 = {0,0,0,0};   // batch 2w   (lane covers 128 cols: lane*4)
    float4 a1 = {0,0,0,0};   // batch 2w+1

    const int nchunk = (len + CHUNK - 1) / CHUNK;
    const int e_of_t = tid >> 3;     // 8 threads per 512B row
    const int sub    = tid & 7;      // 16B slot group within row

    // Issue cp.async loads for chunk c into buffer buf (512 slots, 2/thread).
    auto issue = [&](int c, int buf) {
        int base = c * CHUNK;
        int gi = base + (e_of_t >> 1);   // hmm — see below; use direct mapping
        (void)gi;
        // 512 slots of 16B: slot g = tid + j*256; row = g/8? No: row has 8
        // slots (128 cols * 4B / 16B = 32 slots)? 128*4=512B → 32 x 16B slots.
        // 16 rows x 32 slots = 512 slots; thread does 2.
#pragma unroll
        for (int j = 0; j < 2; j++) {
            int g  = tid + j * 256;
            int rr = g >> 5;             // row within chunk (32 slots/row)
            int sl = g & 31;             // 16B slot within row
            int gidx = base + rr;
            if (gidx >= len) gidx = len - 1;          // dup load, harmless
            unsigned k = s_ent[gidx] & 0xFFFFu;
            const float* src = ((k < NN) ? (Wint + ((size_t)k << 13))
                                         : (Wext + ((size_t)(k - NN) << 13)))
                               + tile * TILE_COLS + sl * 4;
            unsigned dst = (unsigned)__cvta_generic_to_shared(
                &s_row[buf][rr][sl]);
            CP_ASYNC16(dst, src);
        }
    };

    if (nchunk > 0) {
        issue(0, 0);
        CP_COMMIT();
        for (int c = 0; c < nchunk; c++) {
            int buf = c & 1;
            if (c + 1 < nchunk) issue(c + 1, buf ^ 1);
            CP_COMMIT();
            CP_WAIT1();                           // chunk c resident
            __syncthreads();

            int base = c * CHUNK;
            int lim = len - base; if (lim > CHUNK) lim = CHUNK;
            for (int i = 0; i < lim; i++) {
                unsigned m = s_ent[base + i] >> 16;   // warp-uniform
                if (m & (bit0 | bit1)) {
                    float4 v = s_row[buf][i][lane];
                    if (m & bit0) {
                        a0.x += v.x; a0.y += v.y; a0.z += v.z; a0.w += v.w;
                    }
                    if (m & bit1) {
                        a1.x += v.x; a1.y += v.y; a1.z += v.z; a1.w += v.w;
                    }
                }
            }
            __syncthreads();                      // protect buf before reuse
        }
    }

    // Write partials: layout [s][b][8192]; warp w owns batches 2w, 2w+1.
    int colb = tile * TILE_COLS + lane * 4;
    *(float4*)(g_partial + (((size_t)s * BB + 2 * w) << 13) + colb)     = a0;
    *(float4*)(g_partial + (((size_t)s * BB + 2 * w + 1) << 13) + colb) = a1;
}

// ---- Kernel 4: high-occupancy reduce + epilogue + delay shift --------------
// grid 1024 x 256 = 262144 threads (8 per float4):
//   t in [0, BN4)     : reduce 16 partials + membrane epilogue (4 stores)
//   t in [BN4, 8*BN4) : copy ONE delay-slot float4 (slots 1..7)
// out layout: X [0,BN) | V_new [BN,2BN) | a_new [2BN,3BN) | Xd_new [3BN,11BN)
__global__ __launch_bounds__(256)
void k_final(const float4* __restrict__ V4,
             const float4* __restrict__ a4v,
             const float4* __restrict__ Xd4,
             float4* __restrict__ out4) {
    const int BN4 = BN / 4;
    int t = blockIdx.x * 256 + threadIdx.x;

    if (t < BN4) {
        int i = t;
        float4 Vv = V4[i];
        float4 av = a4v[i];

        float4 cur = make_float4(0.f, 0.f, 0.f, 0.f);
#pragma unroll
        for (int s = 0; s < NSPLIT; s++) {
            float4 p = *(const float4*)(&g_partial[(size_t)s * BN + (size_t)i * 4]);
            cur.x += p.x; cur.y += p.y; cur.z += p.z; cur.w += p.w;
        }

        float4 x, an, vn;
        x.x = (Vv.x >= TH0_F + BETA_F * av.x) ? 1.0f : 0.0f;
        x.y = (Vv.y >= TH0_F + BETA_F * av.y) ? 1.0f : 0.0f;
        x.z = (Vv.z >= TH0_F + BETA_F * av.z) ? 1.0f : 0.0f;
        x.w = (Vv.w >= TH0_F + BETA_F * av.w) ? 1.0f : 0.0f;
        an.x = RHO_A_F * av.x + x.x;
        an.y = RHO_A_F * av.y + x.y;
        an.z = RHO_A_F * av.z + x.z;
        an.w = RHO_A_F * av.w + x.w;
        vn.x = ALPHA_F * Vv.x * (1.0f - x.x) + ONE_MINUS_ALPHA_F * cur.x;
        vn.y = ALPHA_F * Vv.y * (1.0f - x.y) + ONE_MINUS_ALPHA_F * cur.y;
        vn.z = ALPHA_F * Vv.z * (1.0f - x.z) + ONE_MINUS_ALPHA_F * cur.z;
        vn.w = ALPHA_F * Vv.w * (1.0f - x.w) + ONE_MINUS_ALPHA_F * cur.w;

        out4[i] = x;               // X
        out4[BN4 + i] = vn;        // V_new
        out4[2 * BN4 + i] = an;    // a_new
        out4[3 * BN4 + i] = x;     // Xd_new slot 0
    } else {
        int u = t - BN4;           // 0 .. 7*BN4-1
        out4[4 * BN4 + u] = Xd4[u];   // Xd_new slots 1..7 = old slots 0..6
    }
}

// ---- Launch ----------------------------------------------------------------
extern "C" void kernel_launch(void* const* d_in, const int* in_sizes, int n_in,
                              void* d_out, int out_size) {
    const float* V    = (const float*)d_in[0];
    const float* a    = (const float*)d_in[1];
    const float* Xd   = (const float*)d_in[2];
    const float* Xext = (const float*)d_in[3];
    const float* Wint = (const float*)d_in[4];
    const float* Wext = (const float*)d_in[5];
    float* out = (float*)d_out;

    k_mask<<<KTOT / 512, 512>>>(Xd, Xext);
    k_compact<<<1, 1024>>>();

    dim3 grid(NTILES, NSPLIT);
    spmm_union<<<grid, 256>>>(Wint, Wext);

    k_final<<<8 * (BN / 4) / 256, 256>>>(
        (const float4*)V, (const float4*)a, (const float4*)Xd, (float4*)out);
}

// round 17
// speedup vs baseline: 1.1784x; 1.1784x over previous
#include <cuda_runtime.h>
#include <cstdint>

// ---- Problem constants -----------------------------------------------------
#define BB 16
#define NN 8192
#define NIN 4096
#define BN (BB * NN)          // 131072
#define KTOT (NN + NIN)       // 12288 virtual rows (W_int then W_ext)
#define NSPLIT 24
#define TILE_COLS 256
#define NTILES (NN / TILE_COLS)   // 32
#define CHUNK 16
#define SEG_MAX 512           // = ceil(KTOT/NSPLIT)

#define ALPHA_F 0.9512294245007140f
#define ONE_MINUS_ALPHA_F (1.0f - 0.9512294245007140f)
#define RHO_A_F 0.9950124791926823f
#define BETA_F 1.8f
#define TH0_F 1.0f

// ---- Device scratch (static globals, allowed) ------------------------------
__device__ unsigned g_umask[KTOT];                  // 16-bit batch mask per row
__device__ unsigned g_ulist[KTOT];                  // packed (mask<<16)|row
__device__ int      g_ucnt;
__device__ float    g_partial[NSPLIT * BB * NN];    // 12.6 MB split-K partials

// ---- cp.async helpers -------------------------------------------------------
#define CP_ASYNC16(dst_smem, src_gmem) \
    asm volatile("cp.async.cg.shared.global [%0], [%1], 16;" \
                 :: "r"(dst_smem), "l"(src_gmem) : "memory")
#define CP_COMMIT() asm volatile("cp.async.commit_group;" ::: "memory")
#define CP_WAIT1()  asm volatile("cp.async.wait_group 1;" ::: "memory")

// ---- Kernel 1: per-row 16-bit batch activity mask --------------------------
__global__ __launch_bounds__(512)
void k_mask(const float* __restrict__ Xd, const float* __restrict__ Xext) {
    int k = blockIdx.x * 512 + threadIdx.x;
    unsigned m = 0;
    if (k < NN) {
#pragma unroll
        for (int b = 0; b < 16; b++)
            m |= (Xd[(size_t)(7 * BB + b) * NN + k] > 0.5f ? 1u : 0u) << b;
    } else {
#pragma unroll
        for (int b = 0; b < 16; b++)
            m |= (Xext[(size_t)b * NIN + (k - NN)] > 0.5f ? 1u : 0u) << b;
    }
    g_umask[k] = m;
}

// ---- Kernel 2: compaction with warp-stripe counting (2 barriers total) -----
__global__ __launch_bounds__(1024)
void k_compact() {
    __shared__ int s_w[32];
    int tid = threadIdx.x, ws = tid >> 5, lane = tid & 31;
    unsigned lt = (1u << lane) - 1u;
    const int base = ws * (KTOT / 32);   // 384 rows per warp

    unsigned bal[12];
    unsigned my[12];
    int cnt = 0;
#pragma unroll
    for (int u = 0; u < 12; u++) {
        unsigned m = g_umask[base + u * 32 + lane];
        my[u] = m;
        bal[u] = __ballot_sync(0xffffffffu, m != 0);
        cnt += __popc(bal[u]);
    }
    if (lane == 0) s_w[ws] = cnt;
    __syncthreads();

    if (ws == 0) {
        int v = s_w[lane];
        int incl = v;
#pragma unroll
        for (int d = 1; d < 32; d <<= 1) {
            int o = __shfl_up_sync(0xffffffffu, incl, d);
            if (lane >= d) incl += o;
        }
        s_w[lane] = incl - v;            // exclusive offsets
        if (lane == 31) g_ucnt = incl;
    }
    __syncthreads();

    int pos = s_w[ws];
#pragma unroll
    for (int u = 0; u < 12; u++) {
        if (my[u])
            g_ulist[pos + __popc(bal[u] & lt)] =
                (my[u] << 16) | (unsigned)(base + u * 32 + lane);
        pos += __popc(bal[u]);
    }
}

// ---- Kernel 3: union-row sparse sum (R13 structure; NSPLIT=24) -------------
// grid (NTILES=32, NSPLIT=24) = 768 CTAs x 256 threads (~5.2 CTAs/SM).
// cp.async stages CHUNK=16 row segments (16 x 1KB) double-buffered in smem;
// warp w accumulates batches {2w, 2w+1} in registers (static indices).
__global__ __launch_bounds__(256)
void spmm_union(const float* __restrict__ Wint,
                const float* __restrict__ Wext) {
    __shared__ unsigned s_ent[SEG_MAX];                  // 2 KB entries
    __shared__ float4   s_row[2][CHUNK][TILE_COLS / 4];  // 2 x 16 KB rows

    const int tile = blockIdx.x;
    const int s    = blockIdx.y;
    const int tid  = threadIdx.x;
    const int w    = tid >> 5;
    const int lane = tid & 31;

    int cnt = g_ucnt;
    int seg = (cnt + NSPLIT - 1) / NSPLIT;
    int start = s * seg;
    int end = start + seg; if (end > cnt) end = cnt;
    int len = end - start; if (len < 0) len = 0;

    // Stage the entry list segment into smem once.
    for (int i = tid; i < len; i += 256) s_ent[i] = g_ulist[start + i];
    __syncthreads();

    const unsigned bit0 = 1u << (2 * w);
    const unsigned bit1 = 2u << (2 * w);
    float4 a00 = {0,0,0,0}, a01 = {0,0,0,0};   // batch 2w
    float4 a10 = {0,0,0,0}, a11 = {0,0,0,0};   // batch 2w+1

    const int nchunk = (len + CHUNK - 1) / CHUNK;
    const int e_of_t = tid >> 4;     // 16 threads per 1KB row
    const int sub    = tid & 15;     // 16B slot group within row

    // Issue cp.async loads for chunk c into buffer buf.
    auto issue = [&](int c, int buf) {
        int base = c * CHUNK;
        int gi = base + e_of_t;
        if (gi >= len) gi = len - 1;             // clamp (harmless dup load)
        unsigned k = s_ent[gi] & 0xFFFFu;
        const float* src = ((k < NN) ? (Wint + ((size_t)k << 13))
                                     : (Wext + ((size_t)(k - NN) << 13)))
                           + tile * TILE_COLS;
#pragma unroll
        for (int j = 0; j < 4; j++) {
            int slot = sub + j * 16;             // 16B slot within 1KB row
            unsigned dst = (unsigned)__cvta_generic_to_shared(
                &s_row[buf][e_of_t][slot]);
            CP_ASYNC16(dst, src + slot * 4);
        }
    };

    if (nchunk > 0) {
        issue(0, 0);
        CP_COMMIT();
        for (int c = 0; c < nchunk; c++) {
            int buf = c & 1;
            if (c + 1 < nchunk) issue(c + 1, buf ^ 1);
            CP_COMMIT();                          // one group per iteration
            CP_WAIT1();                           // chunk c resident
            __syncthreads();

            int base = c * CHUNK;
            int lim = len - base; if (lim > CHUNK) lim = CHUNK;
            for (int i = 0; i < lim; i++) {
                unsigned m = s_ent[base + i] >> 16;   // warp-uniform
                if (m & (bit0 | bit1)) {
                    float4 v0 = s_row[buf][i][lane * 2];
                    float4 v1 = s_row[buf][i][lane * 2 + 1];
                    if (m & bit0) {
                        a00.x += v0.x; a00.y += v0.y; a00.z += v0.z; a00.w += v0.w;
                        a01.x += v1.x; a01.y += v1.y; a01.z += v1.z; a01.w += v1.w;
                    }
                    if (m & bit1) {
                        a10.x += v0.x; a10.y += v0.y; a10.z += v0.z; a10.w += v0.w;
                        a11.x += v1.x; a11.y += v1.y; a11.z += v1.z; a11.w += v1.w;
                    }
                }
            }
            __syncthreads();                      // protect buf before reuse
        }
    }

    // Write partials: layout [s][b][8192]; warp w owns batches 2w, 2w+1.
    int colb = tile * TILE_COLS + lane * 8;
    float* p0 = g_partial + (((size_t)s * BB + 2 * w) << 13) + colb;
    float* p1 = g_partial + (((size_t)s * BB + 2 * w + 1) << 13) + colb;
    *(float4*)(p0)     = a00;
    *(float4*)(p0 + 4) = a01;
    *(float4*)(p1)     = a10;
    *(float4*)(p1 + 4) = a11;
}

// ---- Kernel 4: high-occupancy reduce + epilogue + delay shift --------------
// grid 1024 x 256 = 262144 threads (8 per float4):
//   t in [0, BN4)     : reduce 24 partials + membrane epilogue (4 stores)
//   t in [BN4, 8*BN4) : copy ONE delay-slot float4 (slots 1..7)
// out layout: X [0,BN) | V_new [BN,2BN) | a_new [2BN,3BN) | Xd_new [3BN,11BN)
__global__ __launch_bounds__(256)
void k_final(const float4* __restrict__ V4,
             const float4* __restrict__ a4v,
             const float4* __restrict__ Xd4,
             float4* __restrict__ out4) {
    const int BN4 = BN / 4;
    int t = blockIdx.x * 256 + threadIdx.x;

    if (t < BN4) {
        int i = t;
        float4 Vv = V4[i];
        float4 av = a4v[i];

        float4 cur = make_float4(0.f, 0.f, 0.f, 0.f);
#pragma unroll
        for (int s = 0; s < NSPLIT; s++) {
            float4 p = *(const float4*)(&g_partial[(size_t)s * BN + (size_t)i * 4]);
            cur.x += p.x; cur.y += p.y; cur.z += p.z; cur.w += p.w;
        }

        float4 x, an, vn;
        x.x = (Vv.x >= TH0_F + BETA_F * av.x) ? 1.0f : 0.0f;
        x.y = (Vv.y >= TH0_F + BETA_F * av.y) ? 1.0f : 0.0f;
        x.z = (Vv.z >= TH0_F + BETA_F * av.z) ? 1.0f : 0.0f;
        x.w = (Vv.w >= TH0_F + BETA_F * av.w) ? 1.0f : 0.0f;
        an.x = RHO_A_F * av.x + x.x;
        an.y = RHO_A_F * av.y + x.y;
        an.z = RHO_A_F * av.z + x.z;
        an.w = RHO_A_F * av.w + x.w;
        vn.x = ALPHA_F * Vv.x * (1.0f - x.x) + ONE_MINUS_ALPHA_F * cur.x;
        vn.y = ALPHA_F * Vv.y * (1.0f - x.y) + ONE_MINUS_ALPHA_F * cur.y;
        vn.z = ALPHA_F * Vv.z * (1.0f - x.z) + ONE_MINUS_ALPHA_F * cur.z;
        vn.w = ALPHA_F * Vv.w * (1.0f - x.w) + ONE_MINUS_ALPHA_F * cur.w;

        out4[i] = x;               // X
        out4[BN4 + i] = vn;        // V_new
        out4[2 * BN4 + i] = an;    // a_new
        out4[3 * BN4 + i] = x;     // Xd_new slot 0
    } else {
        int u = t - BN4;           // 0 .. 7*BN4-1
        out4[4 * BN4 + u] = Xd4[u];   // Xd_new slots 1..7 = old slots 0..6
    }
}

// ---- Launch ----------------------------------------------------------------
extern "C" void kernel_launch(void* const* d_in, const int* in_sizes, int n_in,
                              void* d_out, int out_size) {
    const float* V    = (const float*)d_in[0];
    const float* a    = (const float*)d_in[1];
    const float* Xd   = (const float*)d_in[2];
    const float* Xext = (const float*)d_in[3];
    const float* Wint = (const float*)d_in[4];
    const float* Wext = (const float*)d_in[5];
    float* out = (float*)d_out;

    k_mask<<<KTOT / 512, 512>>>(Xd, Xext);
    k_compact<<<1, 1024>>>();

    dim3 grid(NTILES, NSPLIT);
    spmm_union<<<grid, 256>>>(Wint, Wext);

    k_final<<<8 * (BN / 4) / 256, 256>>>(
        (const float4*)V, (const float4*)a, (const float4*)Xd, (float4*)out);
}